// round 1
// baseline (speedup 1.0000x reference)
#include <cuda_runtime.h>
#include <math.h>

#define E 8
#define D 1024
#define NMAX 4096
#define CAP 4096   // per-expert capacity (top-2 distinct => <= NMAX per expert)

#define BM 128
#define BN 128
#define BK 8

// -------- scratch (device globals; no runtime allocation allowed) --------
__device__ float g_H[(size_t)E * CAP * D];   // expert hidden activations
__device__ float g_O[(size_t)E * CAP * D];   // expert outputs (pre-combine)
__device__ int   g_cnt[E];                   // tokens routed per expert
__device__ int   g_tok[E * CAP];             // token id per bucket slot
__device__ int   g_slot[NMAX * 2];           // per (token,k): e*CAP+pos
__device__ float g_wgt[NMAX * 2];            // per (token,k): renormalized weight

__global__ void zero_counts_kernel() {
    if (threadIdx.x < E) g_cnt[threadIdx.x] = 0;
}

// -------- gating: one block (256 threads = 8 warps) per token --------
__global__ void gate_kernel(const float* __restrict__ x,
                            const float* __restrict__ gW,
                            const float* __restrict__ gb,
                            float* __restrict__ gate_prob_out,
                            int N)
{
    int token = blockIdx.x;
    if (token >= N) return;

    __shared__ float sx[D];
    __shared__ float slog[E];

    const float* xr = x + (size_t)token * D;
    for (int i = threadIdx.x; i < D; i += blockDim.x) sx[i] = xr[i];
    __syncthreads();

    int w    = threadIdx.x >> 5;
    int lane = threadIdx.x & 31;

    // each warp computes one expert's logit
    float s = 0.f;
    const float* wr = gW + w * D;
    for (int k = lane; k < D; k += 32) s += sx[k] * wr[k];
    #pragma unroll
    for (int o = 16; o; o >>= 1) s += __shfl_xor_sync(0xffffffffu, s, o);
    if (lane == 0) slog[w] = s + gb[w];
    __syncthreads();

    if (threadIdx.x == 0) {
        float lg[E], p[E];
        float mx = -1e30f;
        #pragma unroll
        for (int e = 0; e < E; e++) { lg[e] = slog[e]; mx = fmaxf(mx, lg[e]); }
        float sum = 0.f;
        #pragma unroll
        for (int e = 0; e < E; e++) { p[e] = expf(lg[e] - mx); sum += p[e]; }
        float inv = 1.f / sum;

        int i0 = 0; float p0 = -1.f;
        #pragma unroll
        for (int e = 0; e < E; e++) {
            p[e] *= inv;
            gate_prob_out[(size_t)token * E + e] = p[e];
            if (p[e] > p0) { p0 = p[e]; i0 = e; }
        }
        int i1 = -1; float p1 = -1.f;
        #pragma unroll
        for (int e = 0; e < E; e++)
            if (e != i0 && p[e] > p1) { p1 = p[e]; i1 = e; }

        // renormalize: softmax over the two top probabilities
        float e1 = expf(p1 - p0);
        float w0 = 1.f / (1.f + e1);
        float w1 = e1 / (1.f + e1);

        int pos0 = atomicAdd(&g_cnt[i0], 1);
        int pos1 = atomicAdd(&g_cnt[i1], 1);
        g_tok[i0 * CAP + pos0] = token;
        g_tok[i1 * CAP + pos1] = token;
        g_slot[token * 2 + 0] = i0 * CAP + pos0;
        g_slot[token * 2 + 1] = i1 * CAP + pos1;
        g_wgt[token * 2 + 0] = w0;
        g_wgt[token * 2 + 1] = w1;
    }
}

// -------- per-expert GEMM: C = act(A @ W_e^T + b_e) --------
// mode 0: A = x rows gathered via bucket; C = g_H; act = relu; bias = b1
// mode 1: A = g_H (dense within expert block); C = g_O; bias = b2
__global__ __launch_bounds__(256)
void expert_gemm_kernel(const float* __restrict__ x,
                        const float* __restrict__ Wglob,   // [E][D][D] (out,in)
                        const float* __restrict__ bglob,   // [E][D]
                        int mode)
{
    int e  = blockIdx.z;
    int ne = g_cnt[e];
    int m0 = blockIdx.x * BM;
    if (m0 >= ne) return;
    int n0 = blockIdx.y * BN;

    __shared__ float As[BK][BM];
    __shared__ float Bs[BK][BN];

    int t    = threadIdx.x;
    int lrow = t >> 1;          // 0..127
    int lcol = (t & 1) * 4;     // 0 or 4

    bool mvalid = (m0 + lrow) < ne;
    const float* Arow;
    if (mode == 0) {
        int tok = mvalid ? g_tok[e * CAP + m0 + lrow] : 0;
        Arow = x + (size_t)tok * D;
    } else {
        int r = mvalid ? (m0 + lrow) : 0;
        Arow = g_H + ((size_t)e * CAP + r) * D;
    }
    const float* Brow = Wglob + ((size_t)e * D + (n0 + lrow)) * D;

    int ty = t >> 4;   // 0..15 (m groups)
    int tx = t & 15;   // 0..15 (n groups)

    float acc[8][8];
    #pragma unroll
    for (int i = 0; i < 8; i++)
        #pragma unroll
        for (int j = 0; j < 8; j++) acc[i][j] = 0.f;

    for (int k0 = 0; k0 < D; k0 += BK) {
        float4 av = mvalid ? *(const float4*)(Arow + k0 + lcol)
                           : make_float4(0.f, 0.f, 0.f, 0.f);
        float4 bv = *(const float4*)(Brow + k0 + lcol);
        As[lcol + 0][lrow] = av.x; As[lcol + 1][lrow] = av.y;
        As[lcol + 2][lrow] = av.z; As[lcol + 3][lrow] = av.w;
        Bs[lcol + 0][lrow] = bv.x; Bs[lcol + 1][lrow] = bv.y;
        Bs[lcol + 2][lrow] = bv.z; Bs[lcol + 3][lrow] = bv.w;
        __syncthreads();

        #pragma unroll
        for (int kk = 0; kk < BK; kk++) {
            float a[8], b[8];
            #pragma unroll
            for (int i = 0; i < 8; i++) a[i] = As[kk][ty * 8 + i];
            #pragma unroll
            for (int j = 0; j < 8; j++) b[j] = Bs[kk][tx * 8 + j];
            #pragma unroll
            for (int i = 0; i < 8; i++)
                #pragma unroll
                for (int j = 0; j < 8; j++)
                    acc[i][j] = fmaf(a[i], b[j], acc[i][j]);
        }
        __syncthreads();
    }

    const float* bias = bglob + (size_t)e * D + n0;
    float* Cbase = (mode == 0) ? g_H : g_O;
    #pragma unroll
    for (int i = 0; i < 8; i++) {
        int m = m0 + ty * 8 + i;
        if (m >= ne) continue;
        float* crow = Cbase + (((size_t)e * CAP + m) * D + n0);
        #pragma unroll
        for (int j = 0; j < 8; j++) {
            float v = acc[i][j] + bias[tx * 8 + j];
            if (mode == 0) v = fmaxf(v, 0.f);
            crow[tx * 8 + j] = v;
        }
    }
}

// -------- combine: y[t] = w0*O[slot0] + w1*O[slot1] --------
__global__ void combine_kernel(float* __restrict__ y, int N)
{
    int token = blockIdx.x;
    if (token >= N) return;
    int   s0 = g_slot[token * 2 + 0];
    int   s1 = g_slot[token * 2 + 1];
    float w0 = g_wgt[token * 2 + 0];
    float w1 = g_wgt[token * 2 + 1];
    const float* o0 = g_O + (size_t)s0 * D;
    const float* o1 = g_O + (size_t)s1 * D;
    float* yr = y + (size_t)token * D;
    for (int i = threadIdx.x; i < D; i += blockDim.x)
        yr[i] = w0 * o0[i] + w1 * o1[i];
}

extern "C" void kernel_launch(void* const* d_in, const int* in_sizes, int n_in,
                              void* d_out, int out_size)
{
    const float* x  = (const float*)d_in[0];
    const float* gW = (const float*)d_in[1];
    const float* gb = (const float*)d_in[2];
    const float* w1 = (const float*)d_in[3];
    const float* b1 = (const float*)d_in[4];
    const float* w2 = (const float*)d_in[5];
    const float* b2 = (const float*)d_in[6];

    int N = in_sizes[0] / D;                 // 4096

    float* y         = (float*)d_out;        // [N, D]
    float* gate_prob = (float*)d_out + (size_t)N * D;  // [N, E]

    zero_counts_kernel<<<1, 32>>>();
    gate_kernel<<<N, 256>>>(x, gW, gb, gate_prob, N);

    dim3 grid((NMAX + BM - 1) / BM, D / BN, E);   // 32 x 8 x 8 (most blocks exit)
    expert_gemm_kernel<<<grid, 256>>>(x, w1, b1, 0);
    expert_gemm_kernel<<<grid, 256>>>(x, w2, b2, 1);

    combine_kernel<<<N, 256>>>(y, N);
}

// round 3
// speedup vs baseline: 2.5364x; 2.5364x over previous
#include <cuda_runtime.h>
#include <math.h>
#include <stdint.h>

#define E 8
#define D 1024
#define NMAX 4096
#define CAP 4096

#define BM 128
#define BN 128
#define KC 32              // K per stage
#define NSTAGE (D / KC)    // 32
#define LDS_PAD 36         // floats per smem row (conflict-free)
#define STG_FLOATS (2 * BM * LDS_PAD)      // A + B per stage = 9216
#define SMEM_BYTES (3 * STG_FLOATS * 4)    // 110592

// ---------------- scratch (device globals; no runtime allocation) ----------------
__device__ float g_H[(size_t)E * CAP * D];
__device__ float g_O[(size_t)E * CAP * D];
__device__ int   g_cnt[E];
__device__ int   g_tok[E * CAP];
__device__ int   g_slot[NMAX * 2];
__device__ float g_wgt[NMAX * 2];

// ---------------- helpers ----------------
__device__ __forceinline__ uint32_t smem_u32(const void* p) {
    uint32_t a;
    asm("{ .reg .u64 t; cvta.to.shared.u64 t, %1; cvt.u32.u64 %0, t; }" : "=r"(a) : "l"(p));
    return a;
}
__device__ __forceinline__ void cp16(uint32_t s, const void* g) {
    asm volatile("cp.async.cg.shared.global [%0], [%1], 16;" :: "r"(s), "l"(g));
}
__device__ __forceinline__ uint32_t cvt_tf32(float v) {
    uint32_t r;
    asm("cvt.rna.tf32.f32 %0, %1;" : "=r"(r) : "f"(v));
    return r;
}
__device__ __forceinline__ void mma_tf32(float* c, const uint32_t* a, const uint32_t* b) {
    asm volatile(
        "mma.sync.aligned.m16n8k8.row.col.f32.tf32.tf32.f32 "
        "{%0,%1,%2,%3}, {%4,%5,%6,%7}, {%8,%9}, {%0,%1,%2,%3};"
        : "+f"(c[0]), "+f"(c[1]), "+f"(c[2]), "+f"(c[3])
        : "r"(a[0]), "r"(a[1]), "r"(a[2]), "r"(a[3]), "r"(b[0]), "r"(b[1]));
}

__global__ void zero_counts_kernel() {
    if (threadIdx.x < E) g_cnt[threadIdx.x] = 0;
}

// ---------------- gating ----------------
__global__ void gate_kernel(const float* __restrict__ x,
                            const float* __restrict__ gW,
                            const float* __restrict__ gb,
                            float* __restrict__ gate_prob_out,
                            int N)
{
    int token = blockIdx.x;
    if (token >= N) return;

    __shared__ float sx[D];
    __shared__ float slog[E];

    const float* xr = x + (size_t)token * D;
    for (int i = threadIdx.x; i < D; i += blockDim.x) sx[i] = xr[i];
    __syncthreads();

    int w = threadIdx.x >> 5, lane = threadIdx.x & 31;
    float s = 0.f;
    const float* wr = gW + w * D;
    for (int k = lane; k < D; k += 32) s += sx[k] * wr[k];
    #pragma unroll
    for (int o = 16; o; o >>= 1) s += __shfl_xor_sync(0xffffffffu, s, o);
    if (lane == 0) slog[w] = s + gb[w];
    __syncthreads();

    if (threadIdx.x == 0) {
        float p[E];
        float mx = -1e30f;
        #pragma unroll
        for (int e = 0; e < E; e++) mx = fmaxf(mx, slog[e]);
        float sum = 0.f;
        #pragma unroll
        for (int e = 0; e < E; e++) { p[e] = expf(slog[e] - mx); sum += p[e]; }
        float inv = 1.f / sum;

        int i0 = 0; float p0 = -1.f;
        #pragma unroll
        for (int e = 0; e < E; e++) {
            p[e] *= inv;
            gate_prob_out[(size_t)token * E + e] = p[e];
            if (p[e] > p0) { p0 = p[e]; i0 = e; }
        }
        int i1 = -1; float p1 = -1.f;
        #pragma unroll
        for (int e = 0; e < E; e++)
            if (e != i0 && p[e] > p1) { p1 = p[e]; i1 = e; }

        float e1 = expf(p1 - p0);
        float w0 = 1.f / (1.f + e1);
        float w1 = e1 / (1.f + e1);

        int pos0 = atomicAdd(&g_cnt[i0], 1);
        int pos1 = atomicAdd(&g_cnt[i1], 1);
        g_tok[i0 * CAP + pos0] = token;
        g_tok[i1 * CAP + pos1] = token;
        g_slot[token * 2 + 0] = i0 * CAP + pos0;
        g_slot[token * 2 + 1] = i1 * CAP + pos1;
        g_wgt[token * 2 + 0] = w0;
        g_wgt[token * 2 + 1] = w1;
    }
}

// ---------------- expert GEMM via mma.sync tf32 ----------------
// C[m,n] = act(sum_k A[m,k] * W[n,k] + bias[n])
// mode 0: A = gathered x rows -> g_H (relu, b1)
// mode 1: A = g_H rows        -> g_O (b2)
__global__ __launch_bounds__(256, 2)
void expert_gemm_mma(const float* __restrict__ x,
                     const float* __restrict__ W,
                     const float* __restrict__ bias,
                     int mode)
{
    int e  = blockIdx.z;
    int ne = g_cnt[e];
    int m0 = blockIdx.x * BM;
    if (m0 >= ne) return;
    int n0 = blockIdx.y * BN;

    extern __shared__ float sm[];
    uint32_t smb = smem_u32(sm);

    int tid  = threadIdx.x;
    int row  = tid >> 1;        // 0..127
    int half = tid & 1;

    // loader pointers: A row `row`, B row (n) `row`
    const float* Aptr;
    if (mode == 0) {
        int tok = (m0 + row < ne) ? g_tok[e * CAP + m0 + row] : 0;
        Aptr = x + (size_t)tok * D;
    } else {
        Aptr = g_H + ((size_t)e * CAP + m0 + row) * D;
    }
    const float* Bptr = W + ((size_t)e * D + n0 + row) * D;

    uint32_t a_sm = smb + (uint32_t)(row * LDS_PAD + half * 16) * 4u;
    uint32_t b_sm = a_sm + (uint32_t)(BM * LDS_PAD) * 4u;

    #define LOAD_STAGE(buf, k0) do {                                      \
        uint32_t _ab = a_sm + (uint32_t)(buf) * (STG_FLOATS * 4);          \
        uint32_t _bb = b_sm + (uint32_t)(buf) * (STG_FLOATS * 4);          \
        const float* _ag = Aptr + (k0) + half * 16;                        \
        const float* _bg = Bptr + (k0) + half * 16;                        \
        cp16(_ab,      _ag);      cp16(_bb,      _bg);                     \
        cp16(_ab + 16, _ag + 4);  cp16(_bb + 16, _bg + 4);                 \
        cp16(_ab + 32, _ag + 8);  cp16(_bb + 32, _bg + 8);                 \
        cp16(_ab + 48, _ag + 12); cp16(_bb + 48, _bg + 12);                \
        asm volatile("cp.async.commit_group;" ::: "memory");               \
    } while (0)

    LOAD_STAGE(0, 0);
    LOAD_STAGE(1, KC);
    LOAD_STAGE(2, 2 * KC);

    int wid = tid >> 5, lane = tid & 31;
    int g  = lane >> 2, tg = lane & 3;
    int wm = (wid >> 1) * 32;       // warp m offset (4 warps in m)
    int wn = (wid & 1) * 64;        // warp n offset (2 warps in n)

    float acc[2][8][4];
    #pragma unroll
    for (int mt = 0; mt < 2; mt++)
        #pragma unroll
        for (int nt = 0; nt < 8; nt++)
            #pragma unroll
            for (int i = 0; i < 4; i++) acc[mt][nt][i] = 0.f;

    #pragma unroll 1
    for (int s = 0; s < NSTAGE; s++) {
        if (s < NSTAGE - 2)      asm volatile("cp.async.wait_group 2;" ::: "memory");
        else if (s == NSTAGE - 2) asm volatile("cp.async.wait_group 1;" ::: "memory");
        else                     asm volatile("cp.async.wait_group 0;" ::: "memory");
        __syncthreads();

        const float* As = sm + (s % 3) * STG_FLOATS;
        const float* Bs = As + BM * LDS_PAD;

        #pragma unroll
        for (int kk = 0; kk < 4; kk++) {
            uint32_t a[2][4], b[8][2];
            #pragma unroll
            for (int mt = 0; mt < 2; mt++) {
                const float* ap = As + (wm + mt * 16 + g) * LDS_PAD + kk * 8 + tg;
                a[mt][0] = cvt_tf32(ap[0]);
                a[mt][1] = cvt_tf32(ap[8 * LDS_PAD]);
                a[mt][2] = cvt_tf32(ap[4]);
                a[mt][3] = cvt_tf32(ap[8 * LDS_PAD + 4]);
            }
            #pragma unroll
            for (int nt = 0; nt < 8; nt++) {
                const float* bp = Bs + (wn + nt * 8 + g) * LDS_PAD + kk * 8 + tg;
                b[nt][0] = cvt_tf32(bp[0]);
                b[nt][1] = cvt_tf32(bp[4]);
            }
            #pragma unroll
            for (int mt = 0; mt < 2; mt++)
                #pragma unroll
                for (int nt = 0; nt < 8; nt++)
                    mma_tf32(acc[mt][nt], a[mt], b[nt]);
        }
        __syncthreads();
        if (s + 3 < NSTAGE) LOAD_STAGE(s % 3, (s + 3) * KC);
    }

    // ---------------- epilogue ----------------
    const float* brow = bias + (size_t)e * D + n0;
    float* Cb = (mode == 0) ? g_H : g_O;

    #pragma unroll
    for (int mt = 0; mt < 2; mt++) {
        #pragma unroll
        for (int rr = 0; rr < 2; rr++) {
            int m = m0 + wm + mt * 16 + rr * 8 + g;
            if (m >= ne) continue;
            float* crow = Cb + ((size_t)e * CAP + m) * D + n0;
            #pragma unroll
            for (int nt = 0; nt < 8; nt++) {
                int col = wn + nt * 8 + tg * 2;
                float v0 = acc[mt][nt][rr * 2 + 0] + brow[col];
                float v1 = acc[mt][nt][rr * 2 + 1] + brow[col + 1];
                if (mode == 0) { v0 = fmaxf(v0, 0.f); v1 = fmaxf(v1, 0.f); }
                float2 v = make_float2(v0, v1);
                *(float2*)(crow + col) = v;
            }
        }
    }
}

// ---------------- combine ----------------
__global__ void combine_kernel(float* __restrict__ y, int N)
{
    int token = blockIdx.x;
    if (token >= N) return;
    int   s0 = g_slot[token * 2 + 0];
    int   s1 = g_slot[token * 2 + 1];
    float w0 = g_wgt[token * 2 + 0];
    float w1 = g_wgt[token * 2 + 1];
    const float* o0 = g_O + (size_t)s0 * D;
    const float* o1 = g_O + (size_t)s1 * D;
    float* yr = y + (size_t)token * D;
    for (int i = threadIdx.x; i < D; i += blockDim.x)
        yr[i] = w0 * o0[i] + w1 * o1[i];
}

extern "C" void kernel_launch(void* const* d_in, const int* in_sizes, int n_in,
                              void* d_out, int out_size)
{
    const float* x  = (const float*)d_in[0];
    const float* gW = (const float*)d_in[1];
    const float* gb = (const float*)d_in[2];
    const float* w1 = (const float*)d_in[3];
    const float* b1 = (const float*)d_in[4];
    const float* w2 = (const float*)d_in[5];
    const float* b2 = (const float*)d_in[6];

    int N = in_sizes[0] / D;   // 4096

    float* y         = (float*)d_out;
    float* gate_prob = (float*)d_out + (size_t)N * D;

    static int smem_set = 0;
    if (!smem_set) {
        cudaFuncSetAttribute(expert_gemm_mma,
                             cudaFuncAttributeMaxDynamicSharedMemorySize, SMEM_BYTES);
        smem_set = 1;
    }

    zero_counts_kernel<<<1, 32>>>();
    gate_kernel<<<N, 256>>>(x, gW, gb, gate_prob, N);

    dim3 grid(NMAX / BM, D / BN, E);   // 32 x 8 x 8, inactive tiles exit early
    expert_gemm_mma<<<grid, 256, SMEM_BYTES>>>(x, w1, b1, 0);
    expert_gemm_mma<<<grid, 256, SMEM_BYTES>>>(x, w2, b2, 1);

    combine_kernel<<<N, 256>>>(y, N);
}